// round 1
// baseline (speedup 1.0000x reference)
#include <cuda_runtime.h>
#include <cuda_bf16.h>
#include <math.h>

// Problem constants (from reference)
#define NSEG 500000
#define HID 128
#define NBLK 4
#define TM 128          // rows per CTA
#define THREADS 256
#define PITCH (HID + 4) // smem pitch to avoid bank conflicts on column reads
#define RMS_EPS 1.1920929e-07f  // jnp.finfo(float32).eps

// Scratch (device globals — no allocation allowed)
__device__ float    g_logits[2000000];
__device__ unsigned g_smax[NSEG];
__device__ float    g_ssum[NSEG];

// Monotone float<->uint encoding for atomicMax over floats
__device__ __forceinline__ unsigned enc_f(float f) {
    unsigned u = __float_as_uint(f);
    return (u & 0x80000000u) ? ~u : (u | 0x80000000u);
}
__device__ __forceinline__ float dec_f(unsigned u) {
    return (u & 0x80000000u) ? __uint_as_float(u ^ 0x80000000u)
                             : __uint_as_float(~u);
}

// ---------------------------------------------------------------------------
// Kernel 0: reset segment max/sum scratch
// ---------------------------------------------------------------------------
__global__ void seg_init_kernel() {
    int i = blockIdx.x * blockDim.x + threadIdx.x;
    if (i < NSEG) {
        g_smax[i] = enc_f(-INFINITY);
        g_ssum[i] = 0.0f;
    }
}

// ---------------------------------------------------------------------------
// Kernel 1: fused MLP (in-proj, 4 res blocks with rmsnorm+relu, out-proj)
//           + per-segment atomic max on the logit
// Dynamic smem layout (floats):
//   h_s  [TM*PITCH]     hidden state
//   g_s  [TM*PITCH]     rmsnormed hidden
//   ws   [16*HID]       transposed weight chunk (also reused for input staging)
//   scale_s [TM], rws_s [HID], bb_s [HID], wout_s [HID]
// ---------------------------------------------------------------------------
__global__ void __launch_bounds__(THREADS, 1)
mlp_kernel(const float* __restrict__ x,      // [N,3]
           const int*   __restrict__ ids,    // [N]
           const float* __restrict__ W_in,   // [HID,3]
           const float* __restrict__ b_in,   // [HID]
           const float* __restrict__ rms_w,  // [NBLK,HID]
           const float* __restrict__ W_res,  // [NBLK,HID,HID]
           const float* __restrict__ b_res,  // [NBLK,HID]
           const float* __restrict__ W_out,  // [1,HID]
           const float* __restrict__ b_out,  // [1]
           int n)
{
    extern __shared__ float smem[];
    float* h_s     = smem;                        // TM*PITCH
    float* g_s     = h_s + TM * PITCH;            // TM*PITCH
    float* ws      = g_s + TM * PITCH;            // 16*HID (2048)
    float* scale_s = ws + 16 * HID;               // TM
    float* rws_s   = scale_s + TM;                // HID
    float* bb_s    = rws_s + HID;                 // HID
    float* wout_s  = bb_s + HID;                  // HID

    const int t    = threadIdx.x;
    const int tx   = t & 15;      // 16 col-groups
    const int ty   = t >> 4;      // 16 row-groups
    const int row0 = blockIdx.x * TM;

    // ---- Stage x, W_in, b_in (reuse ws region: win[384], bin[128], xs[384])
    float* win_s = ws;
    float* bin_s = ws + 384;
    float* xs    = ws + 512;
    for (int i = t; i < TM * 3; i += THREADS) {
        int r = i / 3;
        xs[i] = (row0 + r < n) ? x[(long long)(row0) * 3 + i] : 0.0f;
    }
    for (int i = t; i < HID * 3; i += THREADS) win_s[i] = W_in[i];
    for (int i = t; i < HID; i += THREADS)     bin_s[i] = b_in[i];
    __syncthreads();

    // ---- Input projection: h = x @ W_in^T + b_in
    for (int idx = t; idx < TM * HID; idx += THREADS) {
        int r = idx >> 7, c = idx & 127;
        float acc = bin_s[c];
        acc = fmaf(xs[r * 3 + 0], win_s[c * 3 + 0], acc);
        acc = fmaf(xs[r * 3 + 1], win_s[c * 3 + 1], acc);
        acc = fmaf(xs[r * 3 + 2], win_s[c * 3 + 2], acc);
        h_s[r * PITCH + c] = acc;
    }

    // ---- Residual blocks
    for (int blk = 0; blk < NBLK; blk++) {
        __syncthreads();
        // stage per-block rms weight and bias
        for (int i = t; i < HID; i += THREADS) {
            rws_s[i] = rms_w[blk * HID + i];
            bb_s[i]  = b_res[blk * HID + i];
        }
        // rmsnorm scales (one thread per row, threads 0..127)
        if (t < TM) {
            float ss = 0.0f;
            #pragma unroll 16
            for (int c = 0; c < HID; c++) {
                float v = h_s[t * PITCH + c];
                ss = fmaf(v, v, ss);
            }
            scale_s[t] = rsqrtf(ss * (1.0f / HID) + RMS_EPS);
        }
        __syncthreads();
        // materialize g = h * scale * rms_w
        for (int idx = t; idx < TM * HID; idx += THREADS) {
            int r = idx >> 7, c = idx & 127;
            g_s[r * PITCH + c] = h_s[r * PITCH + c] * scale_s[r] * rws_s[c];
        }

        // GEMM: t[r][c] = sum_k g[r][k] * W[c][k]; 8x8 fragment / thread
        float acc[8][8];
        #pragma unroll
        for (int u = 0; u < 8; u++)
            #pragma unroll
            for (int v = 0; v < 8; v++) acc[u][v] = 0.0f;

        const float* Wb = W_res + blk * HID * HID;
        for (int k0 = 0; k0 < HID; k0 += 16) {
            __syncthreads();   // g ready (first iter) / previous chunk consumed
            // stage transposed chunk: ws[kk][c] = Wb[c][k0+kk]
            #pragma unroll
            for (int j = 0; j < 2; j++) {
                int lin = (t + j * THREADS) * 4;     // 0..2047
                int c   = lin >> 4;
                int kk  = lin & 15;
                float4 v = *(const float4*)&Wb[c * HID + k0 + kk];
                ws[(kk + 0) * HID + c] = v.x;
                ws[(kk + 1) * HID + c] = v.y;
                ws[(kk + 2) * HID + c] = v.z;
                ws[(kk + 3) * HID + c] = v.w;
            }
            __syncthreads();
            #pragma unroll
            for (int kk = 0; kk < 16; kk++) {
                float a[8];
                #pragma unroll
                for (int u = 0; u < 8; u++)
                    a[u] = g_s[(ty * 8 + u) * PITCH + k0 + kk];
                float4 b0 = *(const float4*)&ws[kk * HID + tx * 8];
                float4 b1 = *(const float4*)&ws[kk * HID + tx * 8 + 4];
                float b[8] = {b0.x, b0.y, b0.z, b0.w, b1.x, b1.y, b1.z, b1.w};
                #pragma unroll
                for (int u = 0; u < 8; u++)
                    #pragma unroll
                    for (int v = 0; v < 8; v++)
                        acc[u][v] = fmaf(a[u], b[v], acc[u][v]);
            }
        }
        // epilogue: h += relu(t + b_res)
        #pragma unroll
        for (int u = 0; u < 8; u++) {
            int r = ty * 8 + u;
            #pragma unroll
            for (int v = 0; v < 8; v++) {
                int c = tx * 8 + v;
                float tv = acc[u][v] + bb_s[c];
                h_s[r * PITCH + c] += fmaxf(tv, 0.0f);
            }
        }
    }

    // ---- Output projection + segment max (2 threads per row)
    __syncthreads();
    for (int i = t; i < HID; i += THREADS) wout_s[i] = W_out[i];
    __syncthreads();
    {
        int r = t >> 1, half = t & 1;
        float a = 0.0f;
        int base  = r * PITCH + half * 64;
        int wbase = half * 64;
        #pragma unroll 16
        for (int c = 0; c < 64; c++)
            a = fmaf(h_s[base + c], wout_s[wbase + c], a);
        a += __shfl_xor_sync(0xffffffffu, a, 1);
        int gr = row0 + r;
        if (half == 0 && gr < n) {
            float lg = a + b_out[0];
            g_logits[gr] = lg;
            atomicMax(&g_smax[ids[gr]], enc_f(lg));
        }
    }
}

// ---------------------------------------------------------------------------
// Kernel 2: e = exp(logit - segmax); out = e; atomic segment sum
// ---------------------------------------------------------------------------
__global__ void seg_expsum_kernel(const int* __restrict__ ids,
                                  float* __restrict__ out, int n)
{
    int i = blockIdx.x * blockDim.x + threadIdx.x;
    if (i < n) {
        int s = ids[i];
        float e = expf(g_logits[i] - dec_f(g_smax[s]));
        out[i] = e;
        atomicAdd(&g_ssum[s], e);
    }
}

// ---------------------------------------------------------------------------
// Kernel 3: normalize
// ---------------------------------------------------------------------------
__global__ void seg_norm_kernel(const int* __restrict__ ids,
                                float* __restrict__ out, int n)
{
    int i = blockIdx.x * blockDim.x + threadIdx.x;
    if (i < n) out[i] = out[i] / g_ssum[ids[i]];
}

// ---------------------------------------------------------------------------
extern "C" void kernel_launch(void* const* d_in, const int* in_sizes, int n_in,
                              void* d_out, int out_size)
{
    const float* x     = (const float*)d_in[0];
    const int*   ids   = (const int*)  d_in[1];
    const float* W_in  = (const float*)d_in[2];
    const float* b_in  = (const float*)d_in[3];
    const float* rms_w = (const float*)d_in[4];
    const float* W_res = (const float*)d_in[5];
    const float* b_res = (const float*)d_in[6];
    const float* W_out = (const float*)d_in[7];
    const float* b_out = (const float*)d_in[8];
    float* out = (float*)d_out;
    const int n = in_sizes[1];   // edge_ids_all element count = N

    // Dynamic smem: 2*TM*PITCH + 16*HID + TM + 3*HID floats
    const int smem_bytes =
        (2 * TM * PITCH + 16 * HID + TM + 3 * HID) * (int)sizeof(float);
    cudaFuncSetAttribute(mlp_kernel,
                         cudaFuncAttributeMaxDynamicSharedMemorySize,
                         smem_bytes);

    seg_init_kernel<<<(NSEG + 255) / 256, 256>>>();
    mlp_kernel<<<(n + TM - 1) / TM, THREADS, smem_bytes>>>(
        x, ids, W_in, b_in, rms_w, W_res, b_res, W_out, b_out, n);
    seg_expsum_kernel<<<(n + 255) / 256, 256>>>(ids, out, n);
    seg_norm_kernel<<<(n + 255) / 256, 256>>>(ids, out, n);
}

// round 3
// speedup vs baseline: 4.8298x; 4.8298x over previous
#include <cuda_runtime.h>
#include <cstdint>
#include <math.h>

// Problem constants
#define NSEG 500000
#define HID 128
#define NBLK 4
#define THREADS 256
#define PITCH 132            // floats; conflict-free for frag loads (132%32==4)
#define RMS_EPS 1.1920929e-07f

// Scratch (device globals — no allocation allowed)
__device__ float    g_logits[2000000];
__device__ unsigned g_smax[NSEG];
__device__ float    g_ssum[NSEG];

__device__ __forceinline__ unsigned enc_f(float f) {
    unsigned u = __float_as_uint(f);
    return (u & 0x80000000u) ? ~u : (u | 0x80000000u);
}
__device__ __forceinline__ float dec_f(unsigned u) {
    return (u & 0x80000000u) ? __uint_as_float(u ^ 0x80000000u)
                             : __uint_as_float(~u);
}

__device__ __forceinline__ uint32_t smem_u32(const void* p) {
    uint32_t a;
    asm("{ .reg .u64 t; cvta.to.shared.u64 t, %1; cvt.u32.u64 %0, t; }"
        : "=r"(a) : "l"(p));
    return a;
}
__device__ __forceinline__ uint32_t cvt_tf32(float f) {
    uint32_t r;
    asm("cvt.rna.tf32.f32 %0, %1;" : "=r"(r) : "f"(f));
    return r;
}

#define CP_ASYNC16(dst, src) \
    asm volatile("cp.async.cg.shared.global [%0], [%1], 16;" \
                 :: "r"(dst), "l"(src) : "memory")
#define CP_COMMIT asm volatile("cp.async.commit_group;" ::: "memory")
#define CP_WAIT0  asm volatile("cp.async.wait_group 0;" ::: "memory")

// D(16x8) += A(16x8 row) * B(8x8 col), tf32 inputs, f32 accumulate
#define MMA_TF32(d, a, b0, b1) \
    asm volatile("mma.sync.aligned.m16n8k8.row.col.f32.tf32.tf32.f32 " \
        "{%0,%1,%2,%3}, {%4,%5,%6,%7}, {%8,%9}, {%0,%1,%2,%3};" \
        : "+f"((d)[0]), "+f"((d)[1]), "+f"((d)[2]), "+f"((d)[3]) \
        : "r"((a)[0]), "r"((a)[1]), "r"((a)[2]), "r"((a)[3]), \
          "r"(b0), "r"(b1))

// ---------------------------------------------------------------------------
// Kernel 0: reset segment scratch
// ---------------------------------------------------------------------------
__global__ void seg_init_kernel() {
    int i = blockIdx.x * blockDim.x + threadIdx.x;
    if (i < NSEG) {
        g_smax[i] = enc_f(-INFINITY);
        g_ssum[i] = 0.0f;
    }
}

// ---------------------------------------------------------------------------
// Kernel 1: fused MLP with mma.sync tf32 tensor cores. 128 rows per CTA.
// smem: h_s[128][132], g_s[128][132] (tf32 bits), w_s[128][132] (raw fp32),
//       consts. Weights cp.async-prefetched per res block.
// ---------------------------------------------------------------------------
__global__ void __launch_bounds__(THREADS, 1)
mlp_mma_kernel(const float* __restrict__ x,
               const int*   __restrict__ ids,
               const float* __restrict__ W_in,
               const float* __restrict__ b_in,
               const float* __restrict__ rms_w,
               const float* __restrict__ W_res,
               const float* __restrict__ b_res,
               const float* __restrict__ W_out,
               const float* __restrict__ b_out,
               int n)
{
    extern __shared__ float smem[];
    float* h_s    = smem;                       // 128*PITCH
    float* g_s    = h_s + 128 * PITCH;          // 128*PITCH (tf32 bits)
    float* w_s    = g_s + 128 * PITCH;          // 128*PITCH (fp32)
    float* win_s  = w_s + 128 * PITCH;          // 384
    float* bin_s  = win_s + 384;                // 128
    float* rws_s  = bin_s + 128;                // 512
    float* bbs_s  = rws_s + 512;                // 512
    float* wout_s = bbs_s + 512;                // 128
    float* xs     = wout_s + 128;               // 384

    const int t     = threadIdx.x;
    const int warp  = t >> 5;
    const int lane  = t & 31;
    const int gid   = lane >> 2;      // 0..7
    const int tig   = lane & 3;       // 0..3
    const int warp_m = warp >> 2;     // 0..1  (64-row stripe)
    const int warp_n = warp & 3;      // 0..3  (32-col stripe)
    const int row0  = blockIdx.x * 128;

    // ---- Stage constants + x rows; launch cp.async for W block 0
    for (int i = t; i < 384; i += THREADS) {
        win_s[i] = W_in[i];
        long long gi = (long long)row0 * 3 + i;
        xs[i] = (gi < 3LL * n) ? x[gi] : 0.0f;
    }
    for (int i = t; i < 128; i += THREADS) {
        bin_s[i]  = b_in[i];
        wout_s[i] = W_out[i];
    }
    for (int i = t; i < 512; i += THREADS) {
        rws_s[i] = rms_w[i];
        bbs_s[i] = b_res[i];
    }
    const uint32_t w_base = smem_u32(w_s);
    {
        const float* src = W_res;   // block 0
        #pragma unroll
        for (int i = 0; i < 16; i++) {
            int c  = t + i * THREADS;       // 0..4095 (16B chunks)
            int nr = c >> 5, kq = c & 31;
            CP_ASYNC16(w_base + (uint32_t)(nr * PITCH + kq * 4) * 4,
                       src + nr * HID + kq * 4);
        }
        CP_COMMIT;
    }
    __syncthreads();

    // ---- In-projection: 2 threads per row, 64 cols each (kept thread-local)
    const int r     = t >> 1;
    const int half  = t & 1;
    const int cbase = half * 64;
    {
        float x0 = xs[r * 3], x1 = xs[r * 3 + 1], x2 = xs[r * 3 + 2];
        #pragma unroll
        for (int j = 0; j < 64; j += 4) {
            float4 o;
            int c = cbase + j;
            o.x = fmaf(x2, win_s[(c+0)*3+2], fmaf(x1, win_s[(c+0)*3+1], fmaf(x0, win_s[(c+0)*3+0], bin_s[c+0])));
            o.y = fmaf(x2, win_s[(c+1)*3+2], fmaf(x1, win_s[(c+1)*3+1], fmaf(x0, win_s[(c+1)*3+0], bin_s[c+1])));
            o.z = fmaf(x2, win_s[(c+2)*3+2], fmaf(x1, win_s[(c+2)*3+1], fmaf(x0, win_s[(c+2)*3+0], bin_s[c+2])));
            o.w = fmaf(x2, win_s[(c+3)*3+2], fmaf(x1, win_s[(c+3)*3+1], fmaf(x0, win_s[(c+3)*3+0], bin_s[c+3])));
            *(float4*)&h_s[r * PITCH + c] = o;
        }
    }
    // No barrier needed: rms below reads the same region this thread wrote.

    // ---- Residual blocks
    for (int b = 0; b < NBLK; b++) {
        // rmsnorm (pairwise over 2 threads/row) + write g (tf32 bits)
        float hv[64];
        float ss = 0.0f;
        #pragma unroll
        for (int j = 0; j < 64; j += 4) {
            float4 v = *(const float4*)&h_s[r * PITCH + cbase + j];
            hv[j] = v.x; hv[j+1] = v.y; hv[j+2] = v.z; hv[j+3] = v.w;
            ss = fmaf(v.x, v.x, ss); ss = fmaf(v.y, v.y, ss);
            ss = fmaf(v.z, v.z, ss); ss = fmaf(v.w, v.w, ss);
        }
        ss += __shfl_xor_sync(0xffffffffu, ss, 1);
        const float sc = rsqrtf(ss * (1.0f / HID) + RMS_EPS);
        const float* rw = rws_s + b * HID + cbase;
        #pragma unroll
        for (int j = 0; j < 64; j += 4) {
            uint4 o;
            o.x = cvt_tf32(hv[j+0] * sc * rw[j+0]);
            o.y = cvt_tf32(hv[j+1] * sc * rw[j+1]);
            o.z = cvt_tf32(hv[j+2] * sc * rw[j+2]);
            o.w = cvt_tf32(hv[j+3] * sc * rw[j+3]);
            *(uint4*)&g_s[r * PITCH + cbase + j] = o;
        }
        CP_WAIT0;          // W(b) staged
        __syncthreads();   // g_s + w_s visible to all warps

        // ---- GEMM via mma.sync: warp tile 64r x 32c (4 mt x 4 nt)
        float acc[4][4][4];
        #pragma unroll
        for (int mt = 0; mt < 4; mt++)
            #pragma unroll
            for (int nt = 0; nt < 4; nt++) {
                acc[mt][nt][0] = 0.f; acc[mt][nt][1] = 0.f;
                acc[mt][nt][2] = 0.f; acc[mt][nt][3] = 0.f;
            }
        const uint32_t* gs = (const uint32_t*)g_s;
        const uint32_t* ws = (const uint32_t*)w_s;
        const int m0  = warp_m * 64;
        const int n0w = warp_n * 32;
        #pragma unroll
        for (int ks = 0; ks < 16; ks++) {
            const int k0 = ks * 8;
            uint32_t a[4][4];
            #pragma unroll
            for (int mt = 0; mt < 4; mt++) {
                int rr = m0 + mt * 16 + gid;
                a[mt][0] = gs[rr       * PITCH + k0 + tig];
                a[mt][1] = gs[(rr + 8) * PITCH + k0 + tig];
                a[mt][2] = gs[rr       * PITCH + k0 + tig + 4];
                a[mt][3] = gs[(rr + 8) * PITCH + k0 + tig + 4];
            }
            #pragma unroll
            for (int nt = 0; nt < 4; nt++) {
                int nn = n0w + nt * 8 + gid;
                uint32_t b0 = ws[nn * PITCH + k0 + tig];
                uint32_t b1 = ws[nn * PITCH + k0 + tig + 4];
                #pragma unroll
                for (int mt = 0; mt < 4; mt++)
                    MMA_TF32(acc[mt][nt], a[mt], b0, b1);
            }
        }
        __syncthreads();   // all warps done reading w_s / g_s

        // Prefetch next weight block (overlaps epilogue + next rmsnorm)
        if (b < NBLK - 1) {
            const float* src = W_res + (b + 1) * HID * HID;
            #pragma unroll
            for (int i = 0; i < 16; i++) {
                int c  = t + i * THREADS;
                int nr = c >> 5, kq = c & 31;
                CP_ASYNC16(w_base + (uint32_t)(nr * PITCH + kq * 4) * 4,
                           src + nr * HID + kq * 4);
            }
            CP_COMMIT;
        }

        // ---- Epilogue: h += relu(acc + b_res)
        #pragma unroll
        for (int mt = 0; mt < 4; mt++) {
            int rr = m0 + mt * 16 + gid;
            #pragma unroll
            for (int nt = 0; nt < 4; nt++) {
                int cc = n0w + nt * 8 + 2 * tig;
                float2 bias = *(const float2*)&bbs_s[b * HID + cc];
                float2 h0 = *(float2*)&h_s[rr * PITCH + cc];
                h0.x += fmaxf(acc[mt][nt][0] + bias.x, 0.0f);
                h0.y += fmaxf(acc[mt][nt][1] + bias.y, 0.0f);
                *(float2*)&h_s[rr * PITCH + cc] = h0;
                float2 h1 = *(float2*)&h_s[(rr + 8) * PITCH + cc];
                h1.x += fmaxf(acc[mt][nt][2] + bias.x, 0.0f);
                h1.y += fmaxf(acc[mt][nt][3] + bias.y, 0.0f);
                *(float2*)&h_s[(rr + 8) * PITCH + cc] = h1;
            }
        }
        __syncthreads();   // h complete before next rms / out-proj
    }

    // ---- Output projection + segment max
    {
        float a = 0.0f;
        #pragma unroll
        for (int j = 0; j < 64; j += 4) {
            float4 v = *(const float4*)&h_s[r * PITCH + cbase + j];
            float4 w = *(const float4*)&wout_s[cbase + j];
            a = fmaf(v.x, w.x, a); a = fmaf(v.y, w.y, a);
            a = fmaf(v.z, w.z, a); a = fmaf(v.w, w.w, a);
        }
        a += __shfl_xor_sync(0xffffffffu, a, 1);
        long long gr = (long long)row0 + r;
        if (half == 0 && gr < n) {
            float lg = a + b_out[0];
            g_logits[gr] = lg;
            atomicMax(&g_smax[ids[gr]], enc_f(lg));
        }
    }
}

// ---------------------------------------------------------------------------
// Kernel 2: e = exp(logit - segmax); out = e; atomic segment sum
// ---------------------------------------------------------------------------
__global__ void seg_expsum_kernel(const int* __restrict__ ids,
                                  float* __restrict__ out, int n)
{
    int i = blockIdx.x * blockDim.x + threadIdx.x;
    if (i < n) {
        int s = ids[i];
        float e = expf(g_logits[i] - dec_f(g_smax[s]));
        out[i] = e;
        atomicAdd(&g_ssum[s], e);
    }
}

// ---------------------------------------------------------------------------
// Kernel 3: normalize
// ---------------------------------------------------------------------------
__global__ void seg_norm_kernel(const int* __restrict__ ids,
                                float* __restrict__ out, int n)
{
    int i = blockIdx.x * blockDim.x + threadIdx.x;
    if (i < n) out[i] = out[i] / g_ssum[ids[i]];
}

// ---------------------------------------------------------------------------
extern "C" void kernel_launch(void* const* d_in, const int* in_sizes, int n_in,
                              void* d_out, int out_size)
{
    const float* x     = (const float*)d_in[0];
    const int*   ids   = (const int*)  d_in[1];
    const float* W_in  = (const float*)d_in[2];
    const float* b_in  = (const float*)d_in[3];
    const float* rms_w = (const float*)d_in[4];
    const float* W_res = (const float*)d_in[5];
    const float* b_res = (const float*)d_in[6];
    const float* W_out = (const float*)d_in[7];
    const float* b_out = (const float*)d_in[8];
    float* out = (float*)d_out;
    const int n = in_sizes[1];

    const int smem_bytes =
        (3 * 128 * PITCH + 384 + 128 + 512 + 512 + 128 + 384) * (int)sizeof(float);
    cudaFuncSetAttribute(mlp_mma_kernel,
                         cudaFuncAttributeMaxDynamicSharedMemorySize,
                         smem_bytes);

    seg_init_kernel<<<(NSEG + 255) / 256, 256>>>();
    mlp_mma_kernel<<<(n + 127) / 128, THREADS, smem_bytes>>>(
        x, ids, W_in, b_in, rms_w, W_res, b_res, W_out, b_out, n);
    seg_expsum_kernel<<<(n + 255) / 256, 256>>>(ids, out, n);
    seg_norm_kernel<<<(n + 255) / 256, 256>>>(ids, out, n);
}

// round 4
// speedup vs baseline: 7.7681x; 1.6084x over previous
#include <cuda_runtime.h>
#include <cuda_bf16.h>
#include <cstdint>
#include <math.h>

// Problem constants
#define NSEG 500000
#define HID 128
#define NBLK 4
#define THREADS 256
#define PITCHH 136           // halfs per row for bf16 tiles (16B pad)
#define PITCHF 132           // floats per row for fp32 epilogue scratch
#define RMS_EPS 1.1920929e-07f

// Scratch (device globals — no allocation allowed)
__device__ float         g_logits[2000000];
__device__ unsigned      g_smax[NSEG];
__device__ float         g_ssum[NSEG];
__device__ __nv_bfloat16 g_wbf[NBLK * HID * HID];   // pre-converted weights

__device__ __forceinline__ unsigned enc_f(float f) {
    unsigned u = __float_as_uint(f);
    return (u & 0x80000000u) ? ~u : (u | 0x80000000u);
}
__device__ __forceinline__ float dec_f(unsigned u) {
    return (u & 0x80000000u) ? __uint_as_float(u ^ 0x80000000u)
                             : __uint_as_float(~u);
}
__device__ __forceinline__ uint32_t smem_u32(const void* p) {
    uint32_t a;
    asm("{ .reg .u64 t; cvta.to.shared.u64 t, %1; cvt.u32.u64 %0, t; }"
        : "=r"(a) : "l"(p));
    return a;
}
// pack {lo, hi} floats -> bf16x2 (lo in low half)
__device__ __forceinline__ uint32_t bf16x2(float lo, float hi) {
    uint32_t r;
    asm("cvt.rn.bf16x2.f32 %0, %1, %2;" : "=r"(r) : "f"(hi), "f"(lo));
    return r;
}

#define CP_ASYNC16(dst, src) \
    asm volatile("cp.async.cg.shared.global [%0], [%1], 16;" \
                 :: "r"(dst), "l"(src) : "memory")
#define CP_COMMIT asm volatile("cp.async.commit_group;" ::: "memory")
#define CP_WAIT0  asm volatile("cp.async.wait_group 0;" ::: "memory")

#define LDMATRIX_X4(r0, r1, r2, r3, addr) \
    asm volatile("ldmatrix.sync.aligned.m8n8.x4.shared.b16 {%0,%1,%2,%3}, [%4];" \
                 : "=r"(r0), "=r"(r1), "=r"(r2), "=r"(r3) : "r"(addr))

// D(16x8,f32) += A(16x16 bf16, row) * B(16x8 bf16, col)
#define MMA_BF16(d, a, b0, b1) \
    asm volatile("mma.sync.aligned.m16n8k16.row.col.f32.bf16.bf16.f32 " \
        "{%0,%1,%2,%3}, {%4,%5,%6,%7}, {%8,%9}, {%0,%1,%2,%3};" \
        : "+f"((d)[0]), "+f"((d)[1]), "+f"((d)[2]), "+f"((d)[3]) \
        : "r"((a)[0]), "r"((a)[1]), "r"((a)[2]), "r"((a)[3]), \
          "r"(b0), "r"(b1))

// ---------------------------------------------------------------------------
// Kernel -1: convert W_res fp32 -> bf16 global (runs once per launch, ~2us)
// ---------------------------------------------------------------------------
__global__ void w_convert_kernel(const float* __restrict__ W_res) {
    int i = blockIdx.x * blockDim.x + threadIdx.x;
    if (i < NBLK * HID * HID) g_wbf[i] = __float2bfloat16_rn(W_res[i]);
}

// ---------------------------------------------------------------------------
// Kernel 0: reset segment scratch
// ---------------------------------------------------------------------------
__global__ void seg_init_kernel() {
    int i = blockIdx.x * blockDim.x + threadIdx.x;
    if (i < NSEG) {
        g_smax[i] = enc_f(-INFINITY);
        g_ssum[i] = 0.0f;
    }
}

// ---------------------------------------------------------------------------
// Kernel 1: fused MLP, bf16 mma.m16n8k16 + ldmatrix. 128 rows/CTA.
// h lives in registers (2 threads per row, 64 cols each).
// smem: g_s bf16[128][136], w_s bf16[128][136]; fp32 epilogue scratch t_s
// overlays g_s+w_s (both dead between GEMMs). Consts after.
// ---------------------------------------------------------------------------
__global__ void __launch_bounds__(THREADS, 1)
mlp_mma_kernel(const float* __restrict__ x,
               const int*   __restrict__ ids,
               const float* __restrict__ W_in,
               const float* __restrict__ b_in,
               const float* __restrict__ rms_w,
               const float* __restrict__ b_res,
               const float* __restrict__ W_out,
               const float* __restrict__ b_out,
               int n)
{
    extern __shared__ char smem[];
    __nv_bfloat16* g_s = (__nv_bfloat16*)smem;                 // 128*136*2
    __nv_bfloat16* w_s = g_s + 128 * PITCHH;                   // 128*136*2
    float* t_s   = (float*)smem;                               // overlays g+w
    float* cst   = (float*)(smem + 2 * 128 * PITCHH * 2);
    float* win_s  = cst;          // 384
    float* bin_s  = win_s + 384;  // 128
    float* rws_s  = bin_s + 128;  // 512
    float* bbs_s  = rws_s + 512;  // 512
    float* wout_s = bbs_s + 512;  // 128
    float* xs     = wout_s + 128; // 384

    const int t      = threadIdx.x;
    const int warp   = t >> 5;
    const int lane   = t & 31;
    const int gid    = lane >> 2;
    const int tig    = lane & 3;
    const int warp_m = warp >> 2;       // 0..1 : 64-row stripe
    const int warp_n = warp & 3;        // 0..3 : 32-col stripe
    const int m0     = warp_m * 64;
    const int n0w    = warp_n * 32;
    const int row0   = blockIdx.x * 128;

    const uint32_t gb = smem_u32(g_s);
    const uint32_t wb = smem_u32(w_s);

    // ---- Stage constants + x; cp.async W block 0 (bf16, raw bytes)
    for (int i = t; i < 384; i += THREADS) {
        win_s[i] = W_in[i];
        long long gi = (long long)row0 * 3 + i;
        xs[i] = (gi < 3LL * n) ? x[gi] : 0.0f;
    }
    for (int i = t; i < 128; i += THREADS) {
        bin_s[i]  = b_in[i];
        wout_s[i] = W_out[i];
    }
    for (int i = t; i < 512; i += THREADS) {
        rws_s[i] = rms_w[i];
        bbs_s[i] = b_res[i];
    }
    {
        const __nv_bfloat16* src = g_wbf;   // block 0
        #pragma unroll
        for (int it = 0; it < 8; it++) {
            int i  = t + it * THREADS;      // 0..2047 16B-chunks
            int nr = i >> 4, kc = i & 15;
            CP_ASYNC16(wb + (uint32_t)(nr * PITCHH + kc * 8) * 2,
                       src + nr * HID + kc * 8);
        }
        CP_COMMIT;
    }
    __syncthreads();

    // ---- In-projection into registers: 2 threads/row, 64 cols each
    const int r     = t >> 1;
    const int half  = t & 1;
    const int cbase = half * 64;
    float hv[64];
    {
        float x0 = xs[r * 3], x1 = xs[r * 3 + 1], x2 = xs[r * 3 + 2];
        #pragma unroll
        for (int j = 0; j < 64; j++) {
            int c = cbase + j;
            hv[j] = fmaf(x2, win_s[c * 3 + 2],
                     fmaf(x1, win_s[c * 3 + 1],
                      fmaf(x0, win_s[c * 3 + 0], bin_s[c])));
        }
    }

    // ldmatrix per-lane address components (bytes, fixed per thread)
    const uint32_t a_base = gb + ((uint32_t)(m0 + (lane & 15)) * PITCHH
                                  + (uint32_t)(lane >> 4) * 8) * 2;
    const int b_row = n0w + ((lane >> 4) * 8) + (lane & 7);
    const int b_k   = ((lane >> 3) & 1) * 8;
    const uint32_t b_base = wb + ((uint32_t)b_row * PITCHH + (uint32_t)b_k) * 2;

    // ---- Residual blocks
    for (int b = 0; b < NBLK; b++) {
        // rmsnorm: thread-local + pair shuffle
        float ss = 0.0f;
        #pragma unroll
        for (int j = 0; j < 64; j++) ss = fmaf(hv[j], hv[j], ss);
        ss += __shfl_xor_sync(0xffffffffu, ss, 1);
        const float sc = rsqrtf(ss * (1.0f / HID) + RMS_EPS);

        // g = bf16(h * sc * rms_w) -> g_s (8 x st.v4)
        {
            const float* rw = rws_s + b * HID + cbase;
            uint32_t gaddr = gb + (uint32_t)(r * PITCHH + cbase) * 2;
            #pragma unroll
            for (int jj = 0; jj < 8; jj++) {
                uint32_t p0 = bf16x2(hv[jj*8+0] * sc * rw[jj*8+0],
                                     hv[jj*8+1] * sc * rw[jj*8+1]);
                uint32_t p1 = bf16x2(hv[jj*8+2] * sc * rw[jj*8+2],
                                     hv[jj*8+3] * sc * rw[jj*8+3]);
                uint32_t p2 = bf16x2(hv[jj*8+4] * sc * rw[jj*8+4],
                                     hv[jj*8+5] * sc * rw[jj*8+5]);
                uint32_t p3 = bf16x2(hv[jj*8+6] * sc * rw[jj*8+6],
                                     hv[jj*8+7] * sc * rw[jj*8+7]);
                asm volatile("st.shared.v4.b32 [%0], {%1,%2,%3,%4};"
                             :: "r"(gaddr + jj * 16),
                                "r"(p0), "r"(p1), "r"(p2), "r"(p3) : "memory");
            }
        }
        CP_WAIT0;          // W(b) staged
        __syncthreads();   // g_s + w_s ready

        // ---- GEMM: warp tile 64r x 32c, k-step 16
        float acc[4][4][4];
        #pragma unroll
        for (int mt = 0; mt < 4; mt++)
            #pragma unroll
            for (int nt = 0; nt < 4; nt++) {
                acc[mt][nt][0] = 0.f; acc[mt][nt][1] = 0.f;
                acc[mt][nt][2] = 0.f; acc[mt][nt][3] = 0.f;
            }
        #pragma unroll
        for (int ks = 0; ks < 8; ks++) {
            const uint32_t koff = (uint32_t)ks * 32;  // 16 halfs
            uint32_t a[4][4];
            #pragma unroll
            for (int mt = 0; mt < 4; mt++)
                LDMATRIX_X4(a[mt][0], a[mt][1], a[mt][2], a[mt][3],
                            a_base + (uint32_t)mt * (16 * PITCHH * 2) + koff);
            uint32_t bf[4][2];
            #pragma unroll
            for (int np = 0; np < 2; np++)
                LDMATRIX_X4(bf[np*2][0], bf[np*2][1], bf[np*2+1][0], bf[np*2+1][1],
                            b_base + (uint32_t)np * (16 * PITCHH * 2) + koff);
            #pragma unroll
            for (int nt = 0; nt < 4; nt++)
                #pragma unroll
                for (int mt = 0; mt < 4; mt++)
                    MMA_BF16(acc[mt][nt], a[mt], bf[nt][0], bf[nt][1]);
        }
        __syncthreads();   // mma reads done; g_s/w_s reusable as t_s

        // Prefetch next W block (into w_s region *after* epilogue consumes t_s
        // would clash — w_s IS part of t_s; so prefetch happens next block)

        // ---- Epilogue: t = relu(acc + bias) in fp32 scratch
        #pragma unroll
        for (int mt = 0; mt < 4; mt++) {
            int rr = m0 + mt * 16 + gid;
            #pragma unroll
            for (int nt = 0; nt < 4; nt++) {
                int cc = n0w + nt * 8 + 2 * tig;
                float2 bias = *(const float2*)&bbs_s[b * HID + cc];
                float2 v0, v1;
                v0.x = fmaxf(acc[mt][nt][0] + bias.x, 0.0f);
                v0.y = fmaxf(acc[mt][nt][1] + bias.y, 0.0f);
                v1.x = fmaxf(acc[mt][nt][2] + bias.x, 0.0f);
                v1.y = fmaxf(acc[mt][nt][3] + bias.y, 0.0f);
                *(float2*)&t_s[rr * PITCHF + cc]       = v0;
                *(float2*)&t_s[(rr + 8) * PITCHF + cc] = v1;
            }
        }
        __syncthreads();   // t_s complete

        // h += t (thread's own 64 cols)
        #pragma unroll
        for (int j = 0; j < 64; j += 4) {
            float4 v = *(const float4*)&t_s[r * PITCHF + cbase + j];
            hv[j]   += v.x; hv[j+1] += v.y;
            hv[j+2] += v.z; hv[j+3] += v.w;
        }
        __syncthreads();   // t_s consumed; region free for next g/w

        // cp.async next W block (overlaps next rmsnorm + g write)
        if (b < NBLK - 1) {
            const __nv_bfloat16* src = g_wbf + (b + 1) * HID * HID;
            #pragma unroll
            for (int it = 0; it < 8; it++) {
                int i  = t + it * THREADS;
                int nr = i >> 4, kc = i & 15;
                CP_ASYNC16(wb + (uint32_t)(nr * PITCHH + kc * 8) * 2,
                           src + nr * HID + kc * 8);
            }
            CP_COMMIT;
        }
    }

    // ---- Output projection + segment max
    {
        float a = 0.0f;
        #pragma unroll
        for (int j = 0; j < 64; j++) a = fmaf(hv[j], wout_s[cbase + j], a);
        a += __shfl_xor_sync(0xffffffffu, a, 1);
        long long gr = (long long)row0 + r;
        if (half == 0 && gr < n) {
            float lg = a + b_out[0];
            g_logits[gr] = lg;
            atomicMax(&g_smax[ids[gr]], enc_f(lg));
        }
    }
}

// ---------------------------------------------------------------------------
// Kernel 2: e = exp(logit - segmax); out = e; atomic segment sum
// ---------------------------------------------------------------------------
__global__ void seg_expsum_kernel(const int* __restrict__ ids,
                                  float* __restrict__ out, int n)
{
    int i = blockIdx.x * blockDim.x + threadIdx.x;
    if (i < n) {
        int s = ids[i];
        float e = expf(g_logits[i] - dec_f(g_smax[s]));
        out[i] = e;
        atomicAdd(&g_ssum[s], e);
    }
}

// ---------------------------------------------------------------------------
// Kernel 3: normalize
// ---------------------------------------------------------------------------
__global__ void seg_norm_kernel(const int* __restrict__ ids,
                                float* __restrict__ out, int n)
{
    int i = blockIdx.x * blockDim.x + threadIdx.x;
    if (i < n) out[i] = out[i] / g_ssum[ids[i]];
}

// ---------------------------------------------------------------------------
extern "C" void kernel_launch(void* const* d_in, const int* in_sizes, int n_in,
                              void* d_out, int out_size)
{
    const float* x     = (const float*)d_in[0];
    const int*   ids   = (const int*)  d_in[1];
    const float* W_in  = (const float*)d_in[2];
    const float* b_in  = (const float*)d_in[3];
    const float* rms_w = (const float*)d_in[4];
    const float* W_res = (const float*)d_in[5];
    const float* b_res = (const float*)d_in[6];
    const float* W_out = (const float*)d_in[7];
    const float* b_out = (const float*)d_in[8];
    float* out = (float*)d_out;
    const int n = in_sizes[1];

    const int smem_bytes = 2 * 128 * PITCHH * 2     // g_s + w_s (bf16)
                         + 2048 * (int)sizeof(float); // consts
    cudaFuncSetAttribute(mlp_mma_kernel,
                         cudaFuncAttributeMaxDynamicSharedMemorySize,
                         smem_bytes);

    w_convert_kernel<<<(NBLK * HID * HID + 255) / 256, 256>>>(W_res);
    seg_init_kernel<<<(NSEG + 255) / 256, 256>>>();
    mlp_mma_kernel<<<(n + 127) / 128, THREADS, smem_bytes>>>(
        x, ids, W_in, b_in, rms_w, b_res, W_out, b_out, n);
    seg_expsum_kernel<<<(n + 255) / 256, 256>>>(ids, out, n);
    seg_norm_kernel<<<(n + 255) / 256, 256>>>(ids, out, n);
}

// round 5
// speedup vs baseline: 10.5979x; 1.3643x over previous
#include <cuda_runtime.h>
#include <cuda_bf16.h>
#include <cstdint>
#include <math.h>

// Problem constants
#define NSEG 500000
#define HID 128
#define NBLK 4
#define THREADS 256
#define PITCHH 136           // halfs per bf16 tile row (16B pad)
#define RMS_EPS 1.1920929e-07f

#define TILE_HB (128 * PITCHH * 2)          // bytes per 128x128 bf16 tile
#define OFF_W   0                            // 4 weight tiles
#define OFF_G   (4 * TILE_HB)                // 2 g tiles (double buffer)
#define OFF_RS  (6 * TILE_HB)                // rowsum[128][4] floats
#define OFF_CST (6 * TILE_HB + 2048)         // consts (8192 B)
#define SMEM_TOTAL (OFF_CST + 8192)

// Scratch (device globals — no allocation allowed)
__device__ float         g_logits[2000000];
__device__ unsigned      g_smax[NSEG];
__device__ float         g_ssum[NSEG];
__device__ __nv_bfloat16 g_wbf[NBLK * HID * HID];

__device__ __forceinline__ unsigned enc_f(float f) {
    unsigned u = __float_as_uint(f);
    return (u & 0x80000000u) ? ~u : (u | 0x80000000u);
}
__device__ __forceinline__ float dec_f(unsigned u) {
    return (u & 0x80000000u) ? __uint_as_float(u ^ 0x80000000u)
                             : __uint_as_float(~u);
}
__device__ __forceinline__ uint32_t smem_u32(const void* p) {
    uint32_t a;
    asm("{ .reg .u64 t; cvta.to.shared.u64 t, %1; cvt.u32.u64 %0, t; }"
        : "=r"(a) : "l"(p));
    return a;
}
__device__ __forceinline__ uint32_t bf16x2(float lo, float hi) {
    uint32_t r;
    asm("cvt.rn.bf16x2.f32 %0, %1, %2;" : "=r"(r) : "f"(hi), "f"(lo));
    return r;
}

#define CP_ASYNC16(dst, src) \
    asm volatile("cp.async.cg.shared.global [%0], [%1], 16;" \
                 :: "r"(dst), "l"(src) : "memory")
#define CP_COMMIT asm volatile("cp.async.commit_group;" ::: "memory")
#define CP_WAIT0  asm volatile("cp.async.wait_group 0;" ::: "memory")

#define LDMATRIX_X4(r0, r1, r2, r3, addr) \
    asm volatile("ldmatrix.sync.aligned.m8n8.x4.shared.b16 {%0,%1,%2,%3}, [%4];" \
                 : "=r"(r0), "=r"(r1), "=r"(r2), "=r"(r3) : "r"(addr))

#define MMA_BF16(d, a, b0, b1) \
    asm volatile("mma.sync.aligned.m16n8k16.row.col.f32.bf16.bf16.f32 " \
        "{%0,%1,%2,%3}, {%4,%5,%6,%7}, {%8,%9}, {%0,%1,%2,%3};" \
        : "+f"((d)[0]), "+f"((d)[1]), "+f"((d)[2]), "+f"((d)[3]) \
        : "r"((a)[0]), "r"((a)[1]), "r"((a)[2]), "r"((a)[3]), \
          "r"(b0), "r"(b1))

// ---------------------------------------------------------------------------
__global__ void w_convert_kernel(const float* __restrict__ W_res) {
    int i = blockIdx.x * blockDim.x + threadIdx.x;
    if (i < NBLK * HID * HID) g_wbf[i] = __float2bfloat16_rn(W_res[i]);
}

__global__ void seg_init_kernel() {
    int i = blockIdx.x * blockDim.x + threadIdx.x;
    if (i < NSEG) {
        g_smax[i] = enc_f(-INFINITY);
        g_ssum[i] = 0.0f;
    }
}

// ---------------------------------------------------------------------------
// Fused MLP, h kept in mma-fragment registers end-to-end. 128 rows/CTA.
// All 4 weight tiles staged once; g double-buffered; 2 barriers per block.
// ---------------------------------------------------------------------------
__global__ void __launch_bounds__(THREADS, 1)
mlp_mma_kernel(const float* __restrict__ x,
               const int*   __restrict__ ids,
               const float* __restrict__ W_in,
               const float* __restrict__ b_in,
               const float* __restrict__ rms_w,
               const float* __restrict__ b_res,
               const float* __restrict__ W_out,
               const float* __restrict__ b_out,
               int n)
{
    extern __shared__ char smem[];
    float* rsum   = (float*)(smem + OFF_RS);      // [128][4]
    float* win_s  = (float*)(smem + OFF_CST);     // 384
    float* bin_s  = win_s + 384;                  // 128
    float* rws_s  = bin_s + 128;                  // 512
    float* bbs_s  = rws_s + 512;                  // 512
    float* wout_s = bbs_s + 512;                  // 128
    float* xs     = wout_s + 128;                 // 384

    const int t      = threadIdx.x;
    const int warp   = t >> 5;
    const int lane   = t & 31;
    const int gid    = lane >> 2;       // 0..7 (row within 8-group)
    const int tig    = lane & 3;        // 0..3 (col pair)
    const int warp_m = warp >> 2;       // 0..1
    const int warp_n = warp & 3;        // 0..3
    const int m0     = warp_m * 64;
    const int n0w    = warp_n * 32;
    const int row0   = blockIdx.x * 128;

    const uint32_t wbase = smem_u32(smem + OFF_W);
    const uint32_t gbase = smem_u32(smem + OFF_G);

    // ---- Stage consts + x
    for (int i = t; i < 384; i += THREADS) {
        win_s[i] = W_in[i];
        long long gi = (long long)row0 * 3 + i;
        xs[i] = (gi < 3LL * n) ? x[gi] : 0.0f;
    }
    for (int i = t; i < 128; i += THREADS) {
        bin_s[i]  = b_in[i];
        wout_s[i] = W_out[i];
    }
    for (int i = t; i < 512; i += THREADS) {
        rws_s[i] = rms_w[i];
        bbs_s[i] = b_res[i];
    }
    // ---- Stage ALL 4 weight tiles (bf16, 16B chunks)
    #pragma unroll
    for (int it = 0; it < 32; it++) {
        int i   = t + it * THREADS;     // 0..8191
        int nrg = i >> 4;               // 0..511 (blk*128 + row)
        int kc  = i & 15;
        CP_ASYNC16(wbase + (uint32_t)(nrg * PITCHH + kc * 8) * 2,
                   g_wbf + nrg * HID + kc * 8);
    }
    CP_COMMIT;
    __syncthreads();   // consts + xs visible

    // My 8 columns (pairs): c(nt) = n0w + nt*8 + 2*tig
    // ---- In-projection directly into fragment registers hv[mt][nt][e]
    float hv[64];
    {
        float wc[8][3], bc[8];
        #pragma unroll
        for (int nt = 0; nt < 4; nt++) {
            int c0 = n0w + nt * 8 + 2 * tig;
            #pragma unroll
            for (int k = 0; k < 3; k++) {
                wc[nt * 2 + 0][k] = win_s[c0 * 3 + k];
                wc[nt * 2 + 1][k] = win_s[(c0 + 1) * 3 + k];
            }
            bc[nt * 2 + 0] = bin_s[c0];
            bc[nt * 2 + 1] = bin_s[c0 + 1];
        }
        #pragma unroll
        for (int mt = 0; mt < 4; mt++) {
            int r0 = m0 + mt * 16 + gid;
            float a0 = xs[r0 * 3], a1 = xs[r0 * 3 + 1], a2 = xs[r0 * 3 + 2];
            float d0 = xs[(r0 + 8) * 3], d1 = xs[(r0 + 8) * 3 + 1], d2 = xs[(r0 + 8) * 3 + 2];
            #pragma unroll
            for (int nt = 0; nt < 4; nt++) {
                #pragma unroll
                for (int p = 0; p < 2; p++) {
                    float* w = wc[nt * 2 + p];
                    hv[(mt * 4 + nt) * 4 + p] =
                        fmaf(a2, w[2], fmaf(a1, w[1], fmaf(a0, w[0], bc[nt * 2 + p])));
                    hv[(mt * 4 + nt) * 4 + 2 + p] =
                        fmaf(d2, w[2], fmaf(d1, w[1], fmaf(d0, w[0], bc[nt * 2 + p])));
                }
            }
        }
    }

    // ldmatrix lane addresses
    const uint32_t a_off = ((uint32_t)(m0 + (lane & 15)) * PITCHH
                           + (uint32_t)(lane >> 4) * 8) * 2;
    const int b_row = n0w + ((lane >> 4) * 8) + (lane & 7);
    const uint32_t b_off = ((uint32_t)b_row * PITCHH
                            + (uint32_t)(((lane >> 3) & 1) * 8)) * 2;

    CP_WAIT0;   // all weights staged (well before first GEMM barrier)

    // ---- Residual blocks
    for (int b = 0; b < NBLK; b++) {
        // rms partials: per mt, rows r0 and r0+8 (32-col slice of this warp)
        #pragma unroll
        for (int mt = 0; mt < 4; mt++) {
            float p0 = 0.f, p1 = 0.f;
            #pragma unroll
            for (int nt = 0; nt < 4; nt++) {
                float e0 = hv[(mt*4+nt)*4+0], e1 = hv[(mt*4+nt)*4+1];
                float e2 = hv[(mt*4+nt)*4+2], e3 = hv[(mt*4+nt)*4+3];
                p0 = fmaf(e0, e0, fmaf(e1, e1, p0));
                p1 = fmaf(e2, e2, fmaf(e3, e3, p1));
            }
            p0 += __shfl_xor_sync(0xffffffffu, p0, 1);
            p0 += __shfl_xor_sync(0xffffffffu, p0, 2);
            p1 += __shfl_xor_sync(0xffffffffu, p1, 1);
            p1 += __shfl_xor_sync(0xffffffffu, p1, 2);
            if (tig == 0) {
                int r0 = m0 + mt * 16 + gid;
                rsum[r0 * 4 + warp_n]       = p0;
                rsum[(r0 + 8) * 4 + warp_n] = p1;
            }
        }
        __syncthreads();   // [A] rowsum visible; g[b&1] free of prior readers

        // scales + g write (bf16 fragment -> row-major tile)
        const uint32_t gcur = gbase + (uint32_t)(b & 1) * TILE_HB;
        #pragma unroll
        for (int mt = 0; mt < 4; mt++) {
            int r0 = m0 + mt * 16 + gid;
            float4 s0 = *(const float4*)&rsum[r0 * 4];
            float4 s1 = *(const float4*)&rsum[(r0 + 8) * 4];
            float sc0 = rsqrtf((s0.x + s0.y + s0.z + s0.w) * (1.0f / HID) + RMS_EPS);
            float sc1 = rsqrtf((s1.x + s1.y + s1.z + s1.w) * (1.0f / HID) + RMS_EPS);
            #pragma unroll
            for (int nt = 0; nt < 4; nt++) {
                int c0 = n0w + nt * 8 + 2 * tig;
                float2 rw = *(const float2*)&rws_s[b * HID + c0];
                uint32_t v0 = bf16x2(hv[(mt*4+nt)*4+0] * sc0 * rw.x,
                                     hv[(mt*4+nt)*4+1] * sc0 * rw.y);
                uint32_t v1 = bf16x2(hv[(mt*4+nt)*4+2] * sc1 * rw.x,
                                     hv[(mt*4+nt)*4+3] * sc1 * rw.y);
                asm volatile("st.shared.b32 [%0], %1;"
                    :: "r"(gcur + (uint32_t)(r0 * PITCHH + c0) * 2), "r"(v0) : "memory");
                asm volatile("st.shared.b32 [%0], %1;"
                    :: "r"(gcur + (uint32_t)((r0 + 8) * PITCHH + c0) * 2), "r"(v1) : "memory");
            }
        }
        __syncthreads();   // [B] g tile ready

        // GEMM: warp tile 64r x 32c, k-step 16
        float acc[4][4][4];
        #pragma unroll
        for (int mt = 0; mt < 4; mt++)
            #pragma unroll
            for (int nt = 0; nt < 4; nt++) {
                acc[mt][nt][0] = 0.f; acc[mt][nt][1] = 0.f;
                acc[mt][nt][2] = 0.f; acc[mt][nt][3] = 0.f;
            }
        const uint32_t a_base = gcur + a_off;
        const uint32_t b_base = wbase + (uint32_t)b * TILE_HB + b_off;
        #pragma unroll
        for (int ks = 0; ks < 8; ks++) {
            const uint32_t koff = (uint32_t)ks * 32;
            uint32_t a[4][4];
            #pragma unroll
            for (int mt = 0; mt < 4; mt++)
                LDMATRIX_X4(a[mt][0], a[mt][1], a[mt][2], a[mt][3],
                            a_base + (uint32_t)mt * (16 * PITCHH * 2) + koff);
            uint32_t bf[4][2];
            #pragma unroll
            for (int np = 0; np < 2; np++)
                LDMATRIX_X4(bf[np*2][0], bf[np*2][1], bf[np*2+1][0], bf[np*2+1][1],
                            b_base + (uint32_t)np * (16 * PITCHH * 2) + koff);
            #pragma unroll
            for (int nt = 0; nt < 4; nt++)
                #pragma unroll
                for (int mt = 0; mt < 4; mt++)
                    MMA_BF16(acc[mt][nt], a[mt], bf[nt][0], bf[nt][1]);
        }

        // residual: h += relu(acc + bias) — registers only
        #pragma unroll
        for (int nt = 0; nt < 4; nt++) {
            int c0 = n0w + nt * 8 + 2 * tig;
            float2 bias = *(const float2*)&bbs_s[b * HID + c0];
            #pragma unroll
            for (int mt = 0; mt < 4; mt++) {
                hv[(mt*4+nt)*4+0] += fmaxf(acc[mt][nt][0] + bias.x, 0.0f);
                hv[(mt*4+nt)*4+1] += fmaxf(acc[mt][nt][1] + bias.y, 0.0f);
                hv[(mt*4+nt)*4+2] += fmaxf(acc[mt][nt][2] + bias.x, 0.0f);
                hv[(mt*4+nt)*4+3] += fmaxf(acc[mt][nt][3] + bias.y, 0.0f);
            }
        }
    }

    // ---- Output projection (fragment layout, same reduction path)
    #pragma unroll
    for (int mt = 0; mt < 4; mt++) {
        float o0 = 0.f, o1 = 0.f;
        #pragma unroll
        for (int nt = 0; nt < 4; nt++) {
            int c0 = n0w + nt * 8 + 2 * tig;
            float2 w = *(const float2*)&wout_s[c0];
            o0 = fmaf(hv[(mt*4+nt)*4+0], w.x, fmaf(hv[(mt*4+nt)*4+1], w.y, o0));
            o1 = fmaf(hv[(mt*4+nt)*4+2], w.x, fmaf(hv[(mt*4+nt)*4+3], w.y, o1));
        }
        o0 += __shfl_xor_sync(0xffffffffu, o0, 1);
        o0 += __shfl_xor_sync(0xffffffffu, o0, 2);
        o1 += __shfl_xor_sync(0xffffffffu, o1, 1);
        o1 += __shfl_xor_sync(0xffffffffu, o1, 2);
        if (tig == 0) {
            int r0 = m0 + mt * 16 + gid;
            rsum[r0 * 4 + warp_n]       = o0;
            rsum[(r0 + 8) * 4 + warp_n] = o1;
        }
    }
    __syncthreads();
    if (t < 128) {
        long long gr = (long long)row0 + t;
        if (gr < n) {
            float4 s = *(const float4*)&rsum[t * 4];
            float lg = s.x + s.y + s.z + s.w + b_out[0];
            g_logits[gr] = lg;
            atomicMax(&g_smax[ids[gr]], enc_f(lg));
        }
    }
}

// ---------------------------------------------------------------------------
__global__ void seg_expsum_kernel(const int* __restrict__ ids,
                                  float* __restrict__ out, int n)
{
    int i = blockIdx.x * blockDim.x + threadIdx.x;
    if (i < n) {
        int s = ids[i];
        float e = expf(g_logits[i] - dec_f(g_smax[s]));
        out[i] = e;
        atomicAdd(&g_ssum[s], e);
    }
}

__global__ void seg_norm_kernel(const int* __restrict__ ids,
                                float* __restrict__ out, int n)
{
    int i = blockIdx.x * blockDim.x + threadIdx.x;
    if (i < n) out[i] = out[i] / g_ssum[ids[i]];
}

// ---------------------------------------------------------------------------
extern "C" void kernel_launch(void* const* d_in, const int* in_sizes, int n_in,
                              void* d_out, int out_size)
{
    const float* x     = (const float*)d_in[0];
    const int*   ids   = (const int*)  d_in[1];
    const float* W_in  = (const float*)d_in[2];
    const float* b_in  = (const float*)d_in[3];
    const float* rms_w = (const float*)d_in[4];
    const float* W_res = (const float*)d_in[5];
    const float* b_res = (const float*)d_in[6];
    const float* W_out = (const float*)d_in[7];
    const float* b_out = (const float*)d_in[8];
    float* out = (float*)d_out;
    const int n = in_sizes[1];

    cudaFuncSetAttribute(mlp_mma_kernel,
                         cudaFuncAttributeMaxDynamicSharedMemorySize,
                         SMEM_TOTAL);

    w_convert_kernel<<<(NBLK * HID * HID + 255) / 256, 256>>>(W_res);
    seg_init_kernel<<<(NSEG + 255) / 256, 256>>>();
    mlp_mma_kernel<<<(n + 127) / 128, THREADS, SMEM_TOTAL>>>(
        x, ids, W_in, b_in, rms_w, b_res, W_out, b_out, n);
    seg_expsum_kernel<<<(n + 255) / 256, 256>>>(ids, out, n);
    seg_norm_kernel<<<(n + 255) / 256, 256>>>(ids, out, n);
}

// round 6
// speedup vs baseline: 10.6320x; 1.0032x over previous
#include <cuda_runtime.h>
#include <cuda_bf16.h>
#include <cstdint>
#include <math.h>

// Problem constants
#define NSEG 500000
#define HID 128
#define NBLK 4
#define THREADS 256
#define PITCHH 136           // halfs per bf16 tile row (16B pad, ldmatrix-conflict-free)
#define RMS_EPS 1.1920929e-07f

#define TILE_HB (128 * PITCHH * 2)          // bytes per 128x128 bf16 tile
#define OFF_W   0                            // 4 weight tiles
#define OFF_G   (4 * TILE_HB)                // 1 g tile (half-private rows)
#define OFF_RS  (5 * TILE_HB)                // rowsum[128][4] floats
#define OFF_CST (OFF_RS + 2048)              // consts (8192 B)
#define SMEM_TOTAL (OFF_CST + 8192)

// Scratch (device globals — no allocation allowed)
__device__ float         g_ssum[NSEG];
__device__ __nv_bfloat16 g_wbf[NBLK * HID * HID];

__device__ __forceinline__ uint32_t smem_u32(const void* p) {
    uint32_t a;
    asm("{ .reg .u64 t; cvta.to.shared.u64 t, %1; cvt.u32.u64 %0, t; }"
        : "=r"(a) : "l"(p));
    return a;
}
__device__ __forceinline__ uint32_t bf16x2(float lo, float hi) {
    uint32_t r;
    asm("cvt.rn.bf16x2.f32 %0, %1, %2;" : "=r"(r) : "f"(hi), "f"(lo));
    return r;
}

#define CP_ASYNC16(dst, src) \
    asm volatile("cp.async.cg.shared.global [%0], [%1], 16;" \
                 :: "r"(dst), "l"(src) : "memory")
#define CP_COMMIT asm volatile("cp.async.commit_group;" ::: "memory")
#define CP_WAIT0  asm volatile("cp.async.wait_group 0;" ::: "memory")

// Half-CTA named barrier (128 threads each; ids 1 and 2)
#define BAR_HALF(id) asm volatile("bar.sync %0, 128;" :: "r"(id) : "memory")

#define LDMATRIX_X4(r0, r1, r2, r3, addr) \
    asm volatile("ldmatrix.sync.aligned.m8n8.x4.shared.b16 {%0,%1,%2,%3}, [%4];" \
                 : "=r"(r0), "=r"(r1), "=r"(r2), "=r"(r3) : "r"(addr))

#define MMA_BF16(d, a, b0, b1) \
    asm volatile("mma.sync.aligned.m16n8k16.row.col.f32.bf16.bf16.f32 " \
        "{%0,%1,%2,%3}, {%4,%5,%6,%7}, {%8,%9}, {%0,%1,%2,%3};" \
        : "+f"((d)[0]), "+f"((d)[1]), "+f"((d)[2]), "+f"((d)[3]) \
        : "r"((a)[0]), "r"((a)[1]), "r"((a)[2]), "r"((a)[3]), \
          "r"(b0), "r"(b1))

// ---------------------------------------------------------------------------
__global__ void w_convert_kernel(const float* __restrict__ W_res) {
    int i = blockIdx.x * blockDim.x + threadIdx.x;
    if (i < NBLK * HID * HID) g_wbf[i] = __float2bfloat16_rn(W_res[i]);
}

__global__ void seg_init_kernel() {
    int i = blockIdx.x * blockDim.x + threadIdx.x;
    if (i < NSEG) g_ssum[i] = 0.0f;
}

// ---------------------------------------------------------------------------
// Fused MLP; h in mma-fragment registers end-to-end. 128 rows/CTA.
// CTA split into two independent 64-row halves synced by named barriers,
// so one half's SIMT phases overlap the other half's tensor-core GEMM.
// Epilogue writes e = exp(logit) and atomically accumulates segment sums.
// ---------------------------------------------------------------------------
__global__ void __launch_bounds__(THREADS, 1)
mlp_mma_kernel(const float* __restrict__ x,
               const int*   __restrict__ ids,
               const float* __restrict__ W_in,
               const float* __restrict__ b_in,
               const float* __restrict__ rms_w,
               const float* __restrict__ b_res,
               const float* __restrict__ W_out,
               const float* __restrict__ b_out,
               float* __restrict__ out,
               int n)
{
    extern __shared__ char smem[];
    float* rsum   = (float*)(smem + OFF_RS);      // [128][4]
    float* win_s  = (float*)(smem + OFF_CST);     // 384
    float* bin_s  = win_s + 384;                  // 128
    float* rws_s  = bin_s + 128;                  // 512
    float* bbs_s  = rws_s + 512;                  // 512
    float* wout_s = bbs_s + 512;                  // 128
    float* xs     = wout_s + 128;                 // 384

    const int t      = threadIdx.x;
    const int warp   = t >> 5;
    const int lane   = t & 31;
    const int gid    = lane >> 2;
    const int tig    = lane & 3;
    const int warp_m = warp >> 2;       // 0..1 -> half id
    const int warp_n = warp & 3;
    const int m0     = warp_m * 64;
    const int n0w    = warp_n * 32;
    const int row0   = blockIdx.x * 128;
    const int barid  = 1 + warp_m;

    const uint32_t wbase = smem_u32(smem + OFF_W);
    const uint32_t gbase = smem_u32(smem + OFF_G);

    // ---- Stage consts + x
    for (int i = t; i < 384; i += THREADS) {
        win_s[i] = W_in[i];
        long long gi = (long long)row0 * 3 + i;
        xs[i] = (gi < 3LL * n) ? x[gi] : 0.0f;
    }
    for (int i = t; i < 128; i += THREADS) {
        bin_s[i]  = b_in[i];
        wout_s[i] = W_out[i];
    }
    for (int i = t; i < 512; i += THREADS) {
        rws_s[i] = rms_w[i];
        bbs_s[i] = b_res[i];
    }
    // ---- Stage ALL 4 weight tiles (bf16, 16B chunks)
    #pragma unroll
    for (int it = 0; it < 32; it++) {
        int i   = t + it * THREADS;     // 0..8191
        int nrg = i >> 4;               // blk*128 + row
        int kc  = i & 15;
        CP_ASYNC16(wbase + (uint32_t)(nrg * PITCHH + kc * 8) * 2,
                   g_wbf + nrg * HID + kc * 8);
    }
    CP_COMMIT;
    CP_WAIT0;
    __syncthreads();   // consts + xs + all W tiles visible CTA-wide

    // ---- In-projection directly into fragment registers
    float hv[64];
    {
        float wc[8][3], bc[8];
        #pragma unroll
        for (int nt = 0; nt < 4; nt++) {
            int c0 = n0w + nt * 8 + 2 * tig;
            #pragma unroll
            for (int k = 0; k < 3; k++) {
                wc[nt * 2 + 0][k] = win_s[c0 * 3 + k];
                wc[nt * 2 + 1][k] = win_s[(c0 + 1) * 3 + k];
            }
            bc[nt * 2 + 0] = bin_s[c0];
            bc[nt * 2 + 1] = bin_s[c0 + 1];
        }
        #pragma unroll
        for (int mt = 0; mt < 4; mt++) {
            int r0 = m0 + mt * 16 + gid;
            float a0 = xs[r0 * 3], a1 = xs[r0 * 3 + 1], a2 = xs[r0 * 3 + 2];
            float d0 = xs[(r0 + 8) * 3], d1 = xs[(r0 + 8) * 3 + 1], d2 = xs[(r0 + 8) * 3 + 2];
            #pragma unroll
            for (int nt = 0; nt < 4; nt++) {
                #pragma unroll
                for (int p = 0; p < 2; p++) {
                    float* w = wc[nt * 2 + p];
                    hv[(mt * 4 + nt) * 4 + p] =
                        fmaf(a2, w[2], fmaf(a1, w[1], fmaf(a0, w[0], bc[nt * 2 + p])));
                    hv[(mt * 4 + nt) * 4 + 2 + p] =
                        fmaf(d2, w[2], fmaf(d1, w[1], fmaf(d0, w[0], bc[nt * 2 + p])));
                }
            }
        }
    }

    // ldmatrix lane addresses
    const uint32_t a_off = ((uint32_t)(m0 + (lane & 15)) * PITCHH
                           + (uint32_t)(lane >> 4) * 8) * 2;
    const int b_row = n0w + ((lane >> 4) * 8) + (lane & 7);
    const uint32_t b_off = ((uint32_t)b_row * PITCHH
                            + (uint32_t)(((lane >> 3) & 1) * 8)) * 2;

    // ---- Residual blocks (per-half pipeline; halves skew freely)
    for (int b = 0; b < NBLK; b++) {
        // rms partials into half-private rsum rows
        #pragma unroll
        for (int mt = 0; mt < 4; mt++) {
            float p0 = 0.f, p1 = 0.f;
            #pragma unroll
            for (int nt = 0; nt < 4; nt++) {
                float e0 = hv[(mt*4+nt)*4+0], e1 = hv[(mt*4+nt)*4+1];
                float e2 = hv[(mt*4+nt)*4+2], e3 = hv[(mt*4+nt)*4+3];
                p0 = fmaf(e0, e0, fmaf(e1, e1, p0));
                p1 = fmaf(e2, e2, fmaf(e3, e3, p1));
            }
            p0 += __shfl_xor_sync(0xffffffffu, p0, 1);
            p0 += __shfl_xor_sync(0xffffffffu, p0, 2);
            p1 += __shfl_xor_sync(0xffffffffu, p1, 1);
            p1 += __shfl_xor_sync(0xffffffffu, p1, 2);
            if (tig == 0) {
                int r0 = m0 + mt * 16 + gid;
                rsum[r0 * 4 + warp_n]       = p0;
                rsum[(r0 + 8) * 4 + warp_n] = p1;
            }
        }
        BAR_HALF(barid);   // [A] rowsum visible; half's g rows free of readers

        // scales + g write (bf16, half-private rows)
        #pragma unroll
        for (int mt = 0; mt < 4; mt++) {
            int r0 = m0 + mt * 16 + gid;
            float4 s0 = *(const float4*)&rsum[r0 * 4];
            float4 s1 = *(const float4*)&rsum[(r0 + 8) * 4];
            float sc0 = rsqrtf((s0.x + s0.y + s0.z + s0.w) * (1.0f / HID) + RMS_EPS);
            float sc1 = rsqrtf((s1.x + s1.y + s1.z + s1.w) * (1.0f / HID) + RMS_EPS);
            #pragma unroll
            for (int nt = 0; nt < 4; nt++) {
                int c0 = n0w + nt * 8 + 2 * tig;
                float2 rw = *(const float2*)&rws_s[b * HID + c0];
                uint32_t v0 = bf16x2(hv[(mt*4+nt)*4+0] * sc0 * rw.x,
                                     hv[(mt*4+nt)*4+1] * sc0 * rw.y);
                uint32_t v1 = bf16x2(hv[(mt*4+nt)*4+2] * sc1 * rw.x,
                                     hv[(mt*4+nt)*4+3] * sc1 * rw.y);
                asm volatile("st.shared.b32 [%0], %1;"
                    :: "r"(gbase + (uint32_t)(r0 * PITCHH + c0) * 2), "r"(v0) : "memory");
                asm volatile("st.shared.b32 [%0], %1;"
                    :: "r"(gbase + (uint32_t)((r0 + 8) * PITCHH + c0) * 2), "r"(v1) : "memory");
            }
        }
        BAR_HALF(barid);   // [B] half's g rows ready

        // GEMM: warp tile 64r x 32c, k-step 16 (A rows are half-private)
        float acc[4][4][4];
        #pragma unroll
        for (int mt = 0; mt < 4; mt++)
            #pragma unroll
            for (int nt = 0; nt < 4; nt++) {
                acc[mt][nt][0] = 0.f; acc[mt][nt][1] = 0.f;
                acc[mt][nt][2] = 0.f; acc[mt][nt][3] = 0.f;
            }
        const uint32_t a_base = gbase + a_off;
        const uint32_t b_base = wbase + (uint32_t)b * TILE_HB + b_off;
        #pragma unroll
        for (int ks = 0; ks < 8; ks++) {
            const uint32_t koff = (uint32_t)ks * 32;
            uint32_t a[4][4];
            #pragma unroll
            for (int mt = 0; mt < 4; mt++)
                LDMATRIX_X4(a[mt][0], a[mt][1], a[mt][2], a[mt][3],
                            a_base + (uint32_t)mt * (16 * PITCHH * 2) + koff);
            uint32_t bf[4][2];
            #pragma unroll
            for (int np = 0; np < 2; np++)
                LDMATRIX_X4(bf[np*2][0], bf[np*2][1], bf[np*2+1][0], bf[np*2+1][1],
                            b_base + (uint32_t)np * (16 * PITCHH * 2) + koff);
            #pragma unroll
            for (int nt = 0; nt < 4; nt++)
                #pragma unroll
                for (int mt = 0; mt < 4; mt++)
                    MMA_BF16(acc[mt][nt], a[mt], bf[nt][0], bf[nt][1]);
        }

        // residual: h += relu(acc + bias)
        #pragma unroll
        for (int nt = 0; nt < 4; nt++) {
            int c0 = n0w + nt * 8 + 2 * tig;
            float2 bias = *(const float2*)&bbs_s[b * HID + c0];
            #pragma unroll
            for (int mt = 0; mt < 4; mt++) {
                hv[(mt*4+nt)*4+0] += fmaxf(acc[mt][nt][0] + bias.x, 0.0f);
                hv[(mt*4+nt)*4+1] += fmaxf(acc[mt][nt][1] + bias.y, 0.0f);
                hv[(mt*4+nt)*4+2] += fmaxf(acc[mt][nt][2] + bias.x, 0.0f);
                hv[(mt*4+nt)*4+3] += fmaxf(acc[mt][nt][3] + bias.y, 0.0f);
            }
        }
    }

    // ---- Output projection (per-half reduction)
    #pragma unroll
    for (int mt = 0; mt < 4; mt++) {
        float o0 = 0.f, o1 = 0.f;
        #pragma unroll
        for (int nt = 0; nt < 4; nt++) {
            int c0 = n0w + nt * 8 + 2 * tig;
            float2 w = *(const float2*)&wout_s[c0];
            o0 = fmaf(hv[(mt*4+nt)*4+0], w.x, fmaf(hv[(mt*4+nt)*4+1], w.y, o0));
            o1 = fmaf(hv[(mt*4+nt)*4+2], w.x, fmaf(hv[(mt*4+nt)*4+3], w.y, o1));
        }
        o0 += __shfl_xor_sync(0xffffffffu, o0, 1);
        o0 += __shfl_xor_sync(0xffffffffu, o0, 2);
        o1 += __shfl_xor_sync(0xffffffffu, o1, 1);
        o1 += __shfl_xor_sync(0xffffffffu, o1, 2);
        if (tig == 0) {
            int r0 = m0 + mt * 16 + gid;
            rsum[r0 * 4 + warp_n]       = o0;
            rsum[(r0 + 8) * 4 + warp_n] = o1;
        }
    }
    BAR_HALF(barid);
    // 64 threads of each half finalize their 64 rows: e=exp(logit), seg-sum
    {
        int tid128 = t & 127;
        if (tid128 < 64) {
            int r = m0 + tid128;
            long long gr = (long long)row0 + r;
            if (gr < n) {
                float4 s = *(const float4*)&rsum[r * 4];
                float lg = s.x + s.y + s.z + s.w + b_out[0];
                float e = expf(lg);
                out[gr] = e;
                atomicAdd(&g_ssum[ids[gr]], e);
            }
        }
    }
}

// ---------------------------------------------------------------------------
// Normalize (vectorized): out[i] /= ssum[ids[i]]
// ---------------------------------------------------------------------------
__global__ void seg_norm_kernel(const int* __restrict__ ids,
                                float* __restrict__ out, int n)
{
    int i4 = blockIdx.x * blockDim.x + threadIdx.x;
    int i = i4 * 4;
    if (i + 3 < n) {
        int4   s = *(const int4*)&ids[i];
        float4 v = *(float4*)&out[i];
        v.x /= g_ssum[s.x];
        v.y /= g_ssum[s.y];
        v.z /= g_ssum[s.z];
        v.w /= g_ssum[s.w];
        *(float4*)&out[i] = v;
    } else {
        for (int j = i; j < n; j++) out[j] /= g_ssum[ids[j]];
    }
}

// ---------------------------------------------------------------------------
extern "C" void kernel_launch(void* const* d_in, const int* in_sizes, int n_in,
                              void* d_out, int out_size)
{
    const float* x     = (const float*)d_in[0];
    const int*   ids   = (const int*)  d_in[1];
    const float* W_in  = (const float*)d_in[2];
    const float* b_in  = (const float*)d_in[3];
    const float* rms_w = (const float*)d_in[4];
    const float* W_res = (const float*)d_in[5];
    const float* b_res = (const float*)d_in[6];
    const float* W_out = (const float*)d_in[7];
    const float* b_out = (const float*)d_in[8];
    float* out = (float*)d_out;
    const int n = in_sizes[1];

    cudaFuncSetAttribute(mlp_mma_kernel,
                         cudaFuncAttributeMaxDynamicSharedMemorySize,
                         SMEM_TOTAL);

    w_convert_kernel<<<(NBLK * HID * HID + 255) / 256, 256>>>(W_res);
    seg_init_kernel<<<(NSEG + 255) / 256, 256>>>();
    mlp_mma_kernel<<<(n + 127) / 128, THREADS, SMEM_TOTAL>>>(
        x, ids, W_in, b_in, rms_w, b_res, W_out, b_out, out, n);
    seg_norm_kernel<<<((n + 3) / 4 + 255) / 256, 256>>>(ids, out, n);
}

// round 7
// speedup vs baseline: 12.5867x; 1.1839x over previous
#include <cuda_runtime.h>
#include <cuda_bf16.h>
#include <cstdint>
#include <math.h>

// Problem constants
#define NSEG 500000
#define HID 128
#define NBLK 4
#define THREADS 256
#define NSM 148              // persistent grid size
#define PITCHH 136           // halfs per bf16 tile row (ldmatrix-conflict-free pad)
#define RMS_EPS 1.1920929e-07f

#define TILE_HB (128 * PITCHH * 2)          // bytes per 128x128 bf16 tile (34816)
#define OFF_W   0                            // 4 weight tiles
#define OFF_G   (4 * TILE_HB)                // 1 g tile (half-private rows)
#define OFF_RS  (5 * TILE_HB)                // rowsum[128][4] floats (2048 B)
#define OFF_CST (OFF_RS + 2048)              // consts: 1664 floats (6656 B)
#define OFF_XS  (OFF_CST + 6656)             // xs double buffer 2*384 floats (3072 B)
#define SMEM_TOTAL (OFF_XS + 3072)

// Scratch (device globals — no allocation allowed)
__device__ float         g_ssum[NSEG];
__device__ __nv_bfloat16 g_wbf[NBLK * HID * HID];

__device__ __forceinline__ uint32_t smem_u32(const void* p) {
    uint32_t a;
    asm("{ .reg .u64 t; cvta.to.shared.u64 t, %1; cvt.u32.u64 %0, t; }"
        : "=r"(a) : "l"(p));
    return a;
}
__device__ __forceinline__ uint32_t bf16x2(float lo, float hi) {
    uint32_t r;
    asm("cvt.rn.bf16x2.f32 %0, %1, %2;" : "=r"(r) : "f"(hi), "f"(lo));
    return r;
}

#define CP_ASYNC16(dst, src) \
    asm volatile("cp.async.cg.shared.global [%0], [%1], 16;" \
                 :: "r"(dst), "l"(src) : "memory")
#define CP_COMMIT asm volatile("cp.async.commit_group;" ::: "memory")
#define CP_WAIT0  asm volatile("cp.async.wait_group 0;" ::: "memory")

// Half-CTA named barrier (128 threads each; ids 1 and 2)
#define BAR_HALF(id) asm volatile("bar.sync %0, 128;" :: "r"(id) : "memory")

#define LDMATRIX_X4(r0, r1, r2, r3, addr) \
    asm volatile("ldmatrix.sync.aligned.m8n8.x4.shared.b16 {%0,%1,%2,%3}, [%4];" \
                 : "=r"(r0), "=r"(r1), "=r"(r2), "=r"(r3) : "r"(addr))

#define MMA_BF16(d, a, b0, b1) \
    asm volatile("mma.sync.aligned.m16n8k16.row.col.f32.bf16.bf16.f32 " \
        "{%0,%1,%2,%3}, {%4,%5,%6,%7}, {%8,%9}, {%0,%1,%2,%3};" \
        : "+f"((d)[0]), "+f"((d)[1]), "+f"((d)[2]), "+f"((d)[3]) \
        : "r"((a)[0]), "r"((a)[1]), "r"((a)[2]), "r"((a)[3]), \
          "r"(b0), "r"(b1))

// ---------------------------------------------------------------------------
__global__ void w_convert_kernel(const float* __restrict__ W_res) {
    int i = blockIdx.x * blockDim.x + threadIdx.x;
    if (i < NBLK * HID * HID) g_wbf[i] = __float2bfloat16_rn(W_res[i]);
}

__global__ void seg_init_kernel() {
    int i = blockIdx.x * blockDim.x + threadIdx.x;
    if (i < NSEG) g_ssum[i] = 0.0f;
}

// ---------------------------------------------------------------------------
// Persistent fused MLP: grid=148, each CTA loops over M-tiles of 128 rows.
// Weights staged to smem ONCE per CTA. h in mma-fragment registers.
// Two free-running 64-row halves (named barriers). x double-buffered via
// cp.async so next tile's load hides under current GEMM.
// ---------------------------------------------------------------------------
__global__ void __launch_bounds__(THREADS, 1)
mlp_mma_kernel(const float* __restrict__ x,
               const int*   __restrict__ ids,
               const float* __restrict__ W_in,
               const float* __restrict__ b_in,
               const float* __restrict__ rms_w,
               const float* __restrict__ b_res,
               const float* __restrict__ W_out,
               const float* __restrict__ b_out,
               float* __restrict__ out,
               int n, int ntiles)
{
    extern __shared__ char smem[];
    float* rsum   = (float*)(smem + OFF_RS);      // [128][4]
    float* win_s  = (float*)(smem + OFF_CST);     // 384
    float* bin_s  = win_s + 384;                  // 128
    float* rws_s  = bin_s + 128;                  // 512
    float* bbs_s  = rws_s + 512;                  // 512
    float* wout_s = bbs_s + 512;                  // 128
    float* xs_all = (float*)(smem + OFF_XS);      // [2][384]

    const int t      = threadIdx.x;
    const int warp   = t >> 5;
    const int lane   = t & 31;
    const int gid    = lane >> 2;
    const int tig    = lane & 3;
    const int warp_m = warp >> 2;       // 0..1 -> half id
    const int warp_n = warp & 3;
    const int m0     = warp_m * 64;
    const int n0w    = warp_n * 32;
    const int tid128 = t & 127;
    const int barid  = 1 + warp_m;

    const uint32_t wbase = smem_u32(smem + OFF_W);
    const uint32_t gbase = smem_u32(smem + OFF_G);
    const uint32_t xbase = smem_u32(xs_all);

    // ---- Stage consts once
    for (int i = t; i < 384; i += THREADS) win_s[i] = W_in[i];
    for (int i = t; i < 128; i += THREADS) {
        bin_s[i]  = b_in[i];
        wout_s[i] = W_out[i];
    }
    for (int i = t; i < 512; i += THREADS) {
        rws_s[i] = rms_w[i];
        bbs_s[i] = b_res[i];
    }
    // ---- Stage ALL 4 weight tiles once (bf16, 16B chunks)
    #pragma unroll
    for (int it = 0; it < 32; it++) {
        int i   = t + it * THREADS;     // 0..8191
        int nrg = i >> 4;               // blk*128 + row
        int kc  = i & 15;
        CP_ASYNC16(wbase + (uint32_t)(nrg * PITCHH + kc * 8) * 2,
                   g_wbf + nrg * HID + kc * 8);
    }
    CP_COMMIT;
    CP_WAIT0;
    __syncthreads();   // consts + W visible CTA-wide (last full-CTA barrier)

    const float bout = b_out[0];

    // ldmatrix lane addresses (fixed)
    const uint32_t a_off = ((uint32_t)(m0 + (lane & 15)) * PITCHH
                           + (uint32_t)(lane >> 4) * 8) * 2;
    const int b_row = n0w + ((lane >> 4) * 8) + (lane & 7);
    const uint32_t b_off = ((uint32_t)b_row * PITCHH
                            + (uint32_t)(((lane >> 3) & 1) * 8)) * 2;

    bool pf_next = false;    // next tile's x already prefetched?
    int  buf     = 0;

    for (int tile = blockIdx.x; tile < ntiles; tile += NSM, buf ^= 1) {
        const int row0 = tile * 128;
        float* xsb = xs_all + buf * 384;

        // ---- x for this tile (my half rows m0..m0+63)
        if (pf_next) {
            CP_WAIT0;            // prefetch issued last iteration
        } else {
            for (int i = tid128; i < 192; i += 128) {
                int idx = m0 * 3 + i;
                long long gi = (long long)row0 * 3 + idx;
                xsb[idx] = (gi < 3LL * n) ? x[gi] : 0.0f;
            }
        }
        BAR_HALF(barid);         // xs visible to whole half

        // ---- In-projection into fragment registers
        float hv[64];
        {
            float wc[8][3], bc[8];
            #pragma unroll
            for (int nt = 0; nt < 4; nt++) {
                int c0 = n0w + nt * 8 + 2 * tig;
                #pragma unroll
                for (int k = 0; k < 3; k++) {
                    wc[nt * 2 + 0][k] = win_s[c0 * 3 + k];
                    wc[nt * 2 + 1][k] = win_s[(c0 + 1) * 3 + k];
                }
                bc[nt * 2 + 0] = bin_s[c0];
                bc[nt * 2 + 1] = bin_s[c0 + 1];
            }
            #pragma unroll
            for (int mt = 0; mt < 4; mt++) {
                int r0 = m0 + mt * 16 + gid;
                float a0 = xsb[r0 * 3], a1 = xsb[r0 * 3 + 1], a2 = xsb[r0 * 3 + 2];
                float d0 = xsb[(r0 + 8) * 3], d1 = xsb[(r0 + 8) * 3 + 1], d2 = xsb[(r0 + 8) * 3 + 2];
                #pragma unroll
                for (int nt = 0; nt < 4; nt++) {
                    #pragma unroll
                    for (int p = 0; p < 2; p++) {
                        float* w = wc[nt * 2 + p];
                        hv[(mt * 4 + nt) * 4 + p] =
                            fmaf(a2, w[2], fmaf(a1, w[1], fmaf(a0, w[0], bc[nt * 2 + p])));
                        hv[(mt * 4 + nt) * 4 + 2 + p] =
                            fmaf(d2, w[2], fmaf(d1, w[1], fmaf(d0, w[0], bc[nt * 2 + p])));
                    }
                }
            }
        }

        // ---- Residual blocks
        for (int b = 0; b < NBLK; b++) {
            // rms partials into half-private rsum rows
            #pragma unroll
            for (int mt = 0; mt < 4; mt++) {
                float p0 = 0.f, p1 = 0.f;
                #pragma unroll
                for (int nt = 0; nt < 4; nt++) {
                    float e0 = hv[(mt*4+nt)*4+0], e1 = hv[(mt*4+nt)*4+1];
                    float e2 = hv[(mt*4+nt)*4+2], e3 = hv[(mt*4+nt)*4+3];
                    p0 = fmaf(e0, e0, fmaf(e1, e1, p0));
                    p1 = fmaf(e2, e2, fmaf(e3, e3, p1));
                }
                p0 += __shfl_xor_sync(0xffffffffu, p0, 1);
                p0 += __shfl_xor_sync(0xffffffffu, p0, 2);
                p1 += __shfl_xor_sync(0xffffffffu, p1, 1);
                p1 += __shfl_xor_sync(0xffffffffu, p1, 2);
                if (tig == 0) {
                    int r0 = m0 + mt * 16 + gid;
                    rsum[r0 * 4 + warp_n]       = p0;
                    rsum[(r0 + 8) * 4 + warp_n] = p1;
                }
            }
            BAR_HALF(barid);   // [A] rowsum visible; half's g rows free

            // scales + g write (bf16, half-private rows)
            #pragma unroll
            for (int mt = 0; mt < 4; mt++) {
                int r0 = m0 + mt * 16 + gid;
                float4 s0 = *(const float4*)&rsum[r0 * 4];
                float4 s1 = *(const float4*)&rsum[(r0 + 8) * 4];
                float sc0 = rsqrtf((s0.x + s0.y + s0.z + s0.w) * (1.0f / HID) + RMS_EPS);
                float sc1 = rsqrtf((s1.x + s1.y + s1.z + s1.w) * (1.0f / HID) + RMS_EPS);
                #pragma unroll
                for (int nt = 0; nt < 4; nt++) {
                    int c0 = n0w + nt * 8 + 2 * tig;
                    float2 rw = *(const float2*)&rws_s[b * HID + c0];
                    uint32_t v0 = bf16x2(hv[(mt*4+nt)*4+0] * sc0 * rw.x,
                                         hv[(mt*4+nt)*4+1] * sc0 * rw.y);
                    uint32_t v1 = bf16x2(hv[(mt*4+nt)*4+2] * sc1 * rw.x,
                                         hv[(mt*4+nt)*4+3] * sc1 * rw.y);
                    asm volatile("st.shared.b32 [%0], %1;"
                        :: "r"(gbase + (uint32_t)(r0 * PITCHH + c0) * 2), "r"(v0) : "memory");
                    asm volatile("st.shared.b32 [%0], %1;"
                        :: "r"(gbase + (uint32_t)((r0 + 8) * PITCHH + c0) * 2), "r"(v1) : "memory");
                }
            }
            BAR_HALF(barid);   // [B] half's g rows ready

            // Prefetch next tile's x during block 0 (hides under GEMMs)
            if (b == 0) {
                int nxt = tile + NSM;
                if (nxt < ntiles && (long long)(nxt + 1) * 128 <= (long long)n) {
                    if (tid128 < 48) {
                        uint32_t dst = xbase + (uint32_t)((buf ^ 1) * 1536 + m0 * 12
                                                          + tid128 * 16);
                        const char* src = (const char*)x + (long long)nxt * 1536
                                          + m0 * 12 + tid128 * 16;
                        CP_ASYNC16(dst, src);
                    }
                    CP_COMMIT;
                    pf_next = true;
                } else {
                    pf_next = false;
                }
            }

            // GEMM: warp tile 64r x 32c, k-step 16
            float acc[4][4][4];
            #pragma unroll
            for (int mt = 0; mt < 4; mt++)
                #pragma unroll
                for (int nt = 0; nt < 4; nt++) {
                    acc[mt][nt][0] = 0.f; acc[mt][nt][1] = 0.f;
                    acc[mt][nt][2] = 0.f; acc[mt][nt][3] = 0.f;
                }
            const uint32_t a_base = gbase + a_off;
            const uint32_t b_base = wbase + (uint32_t)b * TILE_HB + b_off;
            #pragma unroll
            for (int ks = 0; ks < 8; ks++) {
                const uint32_t koff = (uint32_t)ks * 32;
                uint32_t a[4][4];
                #pragma unroll
                for (int mt = 0; mt < 4; mt++)
                    LDMATRIX_X4(a[mt][0], a[mt][1], a[mt][2], a[mt][3],
                                a_base + (uint32_t)mt * (16 * PITCHH * 2) + koff);
                uint32_t bf[4][2];
                #pragma unroll
                for (int np = 0; np < 2; np++)
                    LDMATRIX_X4(bf[np*2][0], bf[np*2][1], bf[np*2+1][0], bf[np*2+1][1],
                                b_base + (uint32_t)np * (16 * PITCHH * 2) + koff);
                #pragma unroll
                for (int nt = 0; nt < 4; nt++)
                    #pragma unroll
                    for (int mt = 0; mt < 4; mt++)
                        MMA_BF16(acc[mt][nt], a[mt], bf[nt][0], bf[nt][1]);
            }

            // residual: h += relu(acc + bias)
            #pragma unroll
            for (int nt = 0; nt < 4; nt++) {
                int c0 = n0w + nt * 8 + 2 * tig;
                float2 bias = *(const float2*)&bbs_s[b * HID + c0];
                #pragma unroll
                for (int mt = 0; mt < 4; mt++) {
                    hv[(mt*4+nt)*4+0] += fmaxf(acc[mt][nt][0] + bias.x, 0.0f);
                    hv[(mt*4+nt)*4+1] += fmaxf(acc[mt][nt][1] + bias.y, 0.0f);
                    hv[(mt*4+nt)*4+2] += fmaxf(acc[mt][nt][2] + bias.x, 0.0f);
                    hv[(mt*4+nt)*4+3] += fmaxf(acc[mt][nt][3] + bias.y, 0.0f);
                }
            }
        }

        // ---- Output projection (per-half reduction)
        #pragma unroll
        for (int mt = 0; mt < 4; mt++) {
            float o0 = 0.f, o1 = 0.f;
            #pragma unroll
            for (int nt = 0; nt < 4; nt++) {
                int c0 = n0w + nt * 8 + 2 * tig;
                float2 w = *(const float2*)&wout_s[c0];
                o0 = fmaf(hv[(mt*4+nt)*4+0], w.x, fmaf(hv[(mt*4+nt)*4+1], w.y, o0));
                o1 = fmaf(hv[(mt*4+nt)*4+2], w.x, fmaf(hv[(mt*4+nt)*4+3], w.y, o1));
            }
            o0 += __shfl_xor_sync(0xffffffffu, o0, 1);
            o0 += __shfl_xor_sync(0xffffffffu, o0, 2);
            o1 += __shfl_xor_sync(0xffffffffu, o1, 1);
            o1 += __shfl_xor_sync(0xffffffffu, o1, 2);
            if (tig == 0) {
                int r0 = m0 + mt * 16 + gid;
                rsum[r0 * 4 + warp_n]       = o0;
                rsum[(r0 + 8) * 4 + warp_n] = o1;
            }
        }
        BAR_HALF(barid);
        // 64 threads of the half finalize its 64 rows: e=exp(logit), seg-sum
        if (tid128 < 64) {
            int r = m0 + tid128;
            long long gr = (long long)row0 + r;
            if (gr < n) {
                float4 s = *(const float4*)&rsum[r * 4];
                float lg = s.x + s.y + s.z + s.w + bout;
                float e = expf(lg);
                out[gr] = e;
                atomicAdd(&g_ssum[ids[gr]], e);
            }
        }
        // rsum reads precede next tile's BAR_HALF in program order -> safe reuse
    }
}

// ---------------------------------------------------------------------------
// Normalize (vectorized): out[i] /= ssum[ids[i]]
// ---------------------------------------------------------------------------
__global__ void seg_norm_kernel(const int* __restrict__ ids,
                                float* __restrict__ out, int n)
{
    int i4 = blockIdx.x * blockDim.x + threadIdx.x;
    int i = i4 * 4;
    if (i + 3 < n) {
        int4   s = *(const int4*)&ids[i];
        float4 v = *(float4*)&out[i];
        v.x /= g_ssum[s.x];
        v.y /= g_ssum[s.y];
        v.z /= g_ssum[s.z];
        v.w /= g_ssum[s.w];
        *(float4*)&out[i] = v;
    } else {
        for (int j = i; j < n; j++) out[j] /= g_ssum[ids[j]];
    }
}

// ---------------------------------------------------------------------------
extern "C" void kernel_launch(void* const* d_in, const int* in_sizes, int n_in,
                              void* d_out, int out_size)
{
    const float* x     = (const float*)d_in[0];
    const int*   ids   = (const int*)  d_in[1];
    const float* W_in  = (const float*)d_in[2];
    const float* b_in  = (const float*)d_in[3];
    const float* rms_w = (const float*)d_in[4];
    const float* W_res = (const float*)d_in[5];
    const float* b_res = (const float*)d_in[6];
    const float* W_out = (const float*)d_in[7];
    const float* b_out = (const float*)d_in[8];
    float* out = (float*)d_out;
    const int n = in_sizes[1];
    const int ntiles = (n + 127) / 128;

    cudaFuncSetAttribute(mlp_mma_kernel,
                         cudaFuncAttributeMaxDynamicSharedMemorySize,
                         SMEM_TOTAL);

    w_convert_kernel<<<(NBLK * HID * HID + 255) / 256, 256>>>(W_res);
    seg_init_kernel<<<(NSEG + 255) / 256, 256>>>();
    mlp_mma_kernel<<<NSM, THREADS, SMEM_TOTAL>>>(
        x, ids, W_in, b_in, rms_w, b_res, W_out, b_out, out, n, ntiles);
    seg_norm_kernel<<<((n + 3) / 4 + 255) / 256, 256>>>(ids, out, n);
}